// round 2
// baseline (speedup 1.0000x reference)
#include <cuda_runtime.h>
#include <cstdint>
#include <math.h>

#define N_NODES 50000
#define E_EDGES 800000
#define F_IN    128
#define HID     96
#define L_LAYERS 4

// ---------------- device scratch ----------------
__device__ __align__(16) float g_h   [N_NODES * HID];
__device__ __align__(16) float g_hn  [N_NODES * HID];
__device__ __align__(16) float g_xlxr[N_NODES * 2 * HID];   // stride 192: [0:96)=xl, [96:192)=xr
__device__ __align__(16) int   g_cnt   [N_NODES];
__device__ __align__(16) int   g_rowptr[N_NODES + 1];
__device__ __align__(16) int   g_cursor[N_NODES];
__device__ __align__(16) int   g_csrc  [E_EDGES];   // src sorted by dst (CSR order)
__device__ __align__(16) float g_cew   [E_EDGES];   // edge weight in CSR order
__device__ int g_is64;

// ---------------- edge_index dtype sniff ----------------
__global__ void detect_kernel(const int* ei32) {
    bool is64 = true;
    #pragma unroll
    for (int i = 0; i < 8; i++) if (ei32[2 * i + 1] != 0) is64 = false;
    g_is64 = is64 ? 1 : 0;
}

__device__ __forceinline__ void load_edge(const void* ei, int e, int& s, int& d) {
    if (g_is64) {
        const long long* p = (const long long*)ei;
        s = (int)p[e]; d = (int)p[E_EDGES + e];
    } else {
        const int* p = (const int*)ei;
        s = p[e]; d = p[E_EDGES + e];
    }
}

// ---------------- CSR build ----------------
__global__ void __launch_bounds__(256) hist_kernel(const void* ei) {
    int e = blockIdx.x * blockDim.x + threadIdx.x;
    if (e >= E_EDGES) return;
    int s, d; load_edge(ei, e, s, d);
    atomicAdd(&g_cnt[d], 1);
}

__global__ void __launch_bounds__(1024) scan_kernel() {
    __shared__ int ps[1024];
    int t = threadIdx.x;
    const int CH = (N_NODES + 1023) / 1024;  // 49
    int base = t * CH;
    int sum = 0;
    for (int i = 0; i < CH; i++) {
        int idx = base + i;
        if (idx < N_NODES) sum += g_cnt[idx];
    }
    ps[t] = sum;
    __syncthreads();
    for (int off = 1; off < 1024; off <<= 1) {
        int v = (t >= off) ? ps[t - off] : 0;
        __syncthreads();
        ps[t] += v;
        __syncthreads();
    }
    int run = ps[t] - sum;   // exclusive prefix for this thread's chunk
    for (int i = 0; i < CH; i++) {
        int idx = base + i;
        if (idx < N_NODES) {
            g_rowptr[idx] = run;
            g_cursor[idx] = run;
            run += g_cnt[idx];
        }
    }
    if (t == 0) g_rowptr[N_NODES] = E_EDGES;
}

__global__ void __launch_bounds__(256) scatter_kernel(const void* ei, const float* __restrict__ ew) {
    int e = blockIdx.x * blockDim.x + threadIdx.x;
    if (e >= E_EDGES) return;
    int s, d; load_edge(ei, e, s, d);
    int p = atomicAdd(&g_cursor[d], 1);
    g_csrc[p] = s;
    g_cew[p]  = ew[e];
}

// ---------------- packed-f32x2 helpers ----------------
__device__ __forceinline__ unsigned long long lds64(unsigned addr) {
    unsigned long long v;
    asm volatile("ld.shared.b64 %0, [%1];" : "=l"(v) : "r"(addr));
    return v;
}
__device__ __forceinline__ void ffma2(unsigned long long& d, unsigned long long a, unsigned long long b) {
    asm volatile("fma.rn.f32x2 %0, %1, %2, %0;" : "+l"(d) : "l"(a), "l"(b));
}

// ---------------- GEMM: C[nrows,CW] = A[nrows,K] @ [W1|W2] + [b1|b2] ----------------
// FFMA2 version. A tile stored as duplicated float2 (broadcast operand);
// W column-pairs loaded as b64 (vector operand). Each thread: RPT rows x 3 col-pairs.
template <int K, int CW, int CW1, int CLANES>
__global__ void __launch_bounds__(256) gemm2_kernel(
    const float* __restrict__ A,
    const float* __restrict__ W1, const float* __restrict__ W2,
    const float* __restrict__ b1, const float* __restrict__ b2,
    float* __restrict__ C, int nrows)
{
    constexpr int KCH = 32;
    constexpr int RPB = 64;
    constexpr int RG  = 256 / CLANES;   // row groups
    constexpr int RPT = RPB / RG;       // rows per thread
    constexpr int PS  = CW / 3;         // col-pair stride

    __shared__ float2 As2[RPB * KCH];
    __shared__ float  Ws[KCH * CW];

    const int tid = threadIdx.x;
    const int cx  = tid % CLANES;
    const int ry  = tid / CLANES;
    const int rowbase = blockIdx.x * RPB;

    unsigned aB = (unsigned)__cvta_generic_to_shared(As2);
    unsigned wB = (unsigned)__cvta_generic_to_shared(Ws);

    unsigned long long acc[RPT][3];
    #pragma unroll
    for (int j = 0; j < RPT; j++)
        #pragma unroll
        for (int c = 0; c < 3; c++) acc[j][c] = 0ULL;

    for (int kc = 0; kc < K; kc += KCH) {
        // A tile (64 x 32) -> duplicated float2
        #pragma unroll
        for (int i = 0; i < 2; i++) {
            int f4  = tid + i * 256;
            int row = f4 >> 3;
            int kk  = (f4 & 7) * 4;
            float4 v = make_float4(0.f, 0.f, 0.f, 0.f);
            int grow = rowbase + row;
            if (grow < nrows) v = *(const float4*)(A + (size_t)grow * K + kc + kk);
            As2[row * KCH + kk + 0] = make_float2(v.x, v.x);
            As2[row * KCH + kk + 1] = make_float2(v.y, v.y);
            As2[row * KCH + kk + 2] = make_float2(v.z, v.z);
            As2[row * KCH + kk + 3] = make_float2(v.w, v.w);
        }
        // W tile (32 x CW)
        #pragma unroll
        for (int i = 0; i < (KCH * CW) / 1024; i++) {
            int f = (tid + i * 256) * 4;
            int k = f / CW;
            int c = f % CW;
            float4 v;
            if (c < CW1) v = *(const float4*)(W1 + (size_t)(kc + k) * CW1 + c);
            else         v = *(const float4*)(W2 + (size_t)(kc + k) * (CW - CW1) + (c - CW1));
            *(float4*)(Ws + k * CW + c) = v;
        }
        __syncthreads();

        #pragma unroll 8
        for (int kk = 0; kk < KCH; kk++) {
            unsigned long long av[RPT];
            #pragma unroll
            for (int j = 0; j < RPT; j++)
                av[j] = lds64(aB + (unsigned)(((ry + RG * j) * KCH + kk) << 3));
            unsigned long long wv[3];
            #pragma unroll
            for (int c = 0; c < 3; c++)
                wv[c] = lds64(wB + (unsigned)((kk * CW + 2 * cx + PS * c) << 2));
            #pragma unroll
            for (int j = 0; j < RPT; j++)
                #pragma unroll
                for (int c = 0; c < 3; c++) ffma2(acc[j][c], av[j], wv[c]);
        }
        __syncthreads();
    }

    #pragma unroll
    for (int c = 0; c < 3; c++) {
        int col = 2 * cx + PS * c;
        float bv0, bv1;
        if (col < CW1) { bv0 = b1[col];       bv1 = b1[col + 1]; }
        else           { bv0 = b2[col - CW1]; bv1 = b2[col - CW1 + 1]; }
        #pragma unroll
        for (int j = 0; j < RPT; j++) {
            int grow = rowbase + ry + RG * j;
            if (grow < nrows) {
                float lo, hi;
                asm("mov.b64 {%0,%1}, %2;" : "=f"(lo), "=f"(hi) : "l"(acc[j][c]));
                *(float2*)(C + (size_t)grow * CW + col) = make_float2(lo + bv0, hi + bv1);
            }
        }
    }
}

// ---------------- warp reduce ----------------
__device__ __forceinline__ float wsum(float v) {
    #pragma unroll
    for (int o = 16; o > 0; o >>= 1) v += __shfl_xor_sync(0xffffffffu, v, o);
    return v;
}

// ---------------- initial LayerNorm + ReLU (h -> hn) ----------------
__global__ void __launch_bounds__(256) ln_init_kernel(
    const float* __restrict__ h,
    const float* __restrict__ g, const float* __restrict__ b,
    float* __restrict__ hn)
{
    int warp = threadIdx.x >> 5;
    int lane = threadIdx.x & 31;
    int n = blockIdx.x * 8 + warp;
    if (n >= N_NODES) return;
    size_t base = (size_t)n * HID;

    float v0 = h[base + lane], v1 = h[base + lane + 32], v2 = h[base + lane + 64];
    float mean = wsum(v0 + v1 + v2) * (1.0f / HID);
    float d0 = v0 - mean, d1 = v1 - mean, d2 = v2 - mean;
    float rstd = rsqrtf(wsum(fmaf(d0, d0, fmaf(d1, d1, d2 * d2))) * (1.0f / HID) + 1e-5f);
    hn[base + lane]      = fmaxf(fmaf(d0 * rstd, g[lane],      b[lane]),      0.f);
    hn[base + lane + 32] = fmaxf(fmaf(d1 * rstd, g[lane + 32], b[lane + 32]), 0.f);
    hn[base + lane + 64] = fmaxf(fmaf(d2 * rstd, g[lane + 64], b[lane + 64]), 0.f);
}

// ---------------- fused GAT layer: online-softmax attention + aggregate
//                  + residual + bias + LayerNorm + ReLU  (warp per node, CSR) ---------
__global__ void __launch_bounds__(256) gat_fused_kernel(
    const float* __restrict__ We,  const float* __restrict__ att,
    const float* __restrict__ bias,
    const float* __restrict__ lg,  const float* __restrict__ lb)
{
    __shared__ float sWe[HID], sAtt[HID], sBias[HID], sG[HID], sB[HID];
    int t = threadIdx.x;
    if (t < HID) {
        sWe[t] = We[t]; sAtt[t] = att[t]; sBias[t] = bias[t];
        sG[t] = lg[t];  sB[t]  = lb[t];
    }
    __syncthreads();

    int warp = t >> 5, lane = t & 31;
    int n = blockIdx.x * 8 + warp;
    if (n >= N_NODES) return;

    int r0 = g_rowptr[n], r1 = g_rowptr[n + 1];
    const float* xrp = g_xlxr + (size_t)n * 192 + 96;
    float xr0 = xrp[lane], xr1 = xrp[lane + 32], xr2 = xrp[lane + 64];
    float we0 = sWe[lane],  we1 = sWe[lane + 32],  we2 = sWe[lane + 64];
    float at0 = sAtt[lane], at1 = sAtt[lane + 32], at2 = sAtt[lane + 64];

    float m = -INFINITY, ssum = 0.f;
    float a0 = 0.f, a1 = 0.f, a2 = 0.f;

    int p = r0;
    // 2-edge unrolled online softmax + aggregation
    for (; p + 2 <= r1; p += 2) {
        int   sa = g_csrc[p],   sb = g_csrc[p + 1];
        float wa = g_cew[p],    wb = g_cew[p + 1];
        const float* xa = g_xlxr + (size_t)sa * 192;
        const float* xb = g_xlxr + (size_t)sb * 192;
        float xa0 = xa[lane], xa1 = xa[lane + 32], xa2 = xa[lane + 64];
        float xb0 = xb[lane], xb1 = xb[lane + 32], xb2 = xb[lane + 64];

        float e0 = xa0 + xr0 + wa * we0; e0 = e0 > 0.f ? e0 : 0.2f * e0;
        float e1 = xa1 + xr1 + wa * we1; e1 = e1 > 0.f ? e1 : 0.2f * e1;
        float e2 = xa2 + xr2 + wa * we2; e2 = e2 > 0.f ? e2 : 0.2f * e2;
        float ta = fmaf(e0, at0, fmaf(e1, at1, e2 * at2));

        float f0 = xb0 + xr0 + wb * we0; f0 = f0 > 0.f ? f0 : 0.2f * f0;
        float f1 = xb1 + xr1 + wb * we1; f1 = f1 > 0.f ? f1 : 0.2f * f1;
        float f2 = xb2 + xr2 + wb * we2; f2 = f2 > 0.f ? f2 : 0.2f * f2;
        float tb = fmaf(f0, at0, fmaf(f1, at1, f2 * at2));

        #pragma unroll
        for (int o = 16; o > 0; o >>= 1) {
            ta += __shfl_xor_sync(0xffffffffu, ta, o);
            tb += __shfl_xor_sync(0xffffffffu, tb, o);
        }

        float nm = fmaxf(m, fmaxf(ta, tb));
        float corr = __expf(m - nm);
        float pa = __expf(ta - nm);
        float pb = __expf(tb - nm);
        ssum = fmaf(ssum, corr, pa + pb);
        a0 = fmaf(a0, corr, fmaf(pa, xa0, pb * xb0));
        a1 = fmaf(a1, corr, fmaf(pa, xa1, pb * xb1));
        a2 = fmaf(a2, corr, fmaf(pa, xa2, pb * xb2));
        m = nm;
    }
    if (p < r1) {
        int   sa = g_csrc[p];
        float wa = g_cew[p];
        const float* xa = g_xlxr + (size_t)sa * 192;
        float xa0 = xa[lane], xa1 = xa[lane + 32], xa2 = xa[lane + 64];
        float e0 = xa0 + xr0 + wa * we0; e0 = e0 > 0.f ? e0 : 0.2f * e0;
        float e1 = xa1 + xr1 + wa * we1; e1 = e1 > 0.f ? e1 : 0.2f * e1;
        float e2 = xa2 + xr2 + wa * we2; e2 = e2 > 0.f ? e2 : 0.2f * e2;
        float ta = fmaf(e0, at0, fmaf(e1, at1, e2 * at2));
        #pragma unroll
        for (int o = 16; o > 0; o >>= 1) ta += __shfl_xor_sync(0xffffffffu, ta, o);
        float nm = fmaxf(m, ta);
        float corr = __expf(m - nm);
        float pa = __expf(ta - nm);
        ssum = fmaf(ssum, corr, pa);
        a0 = fmaf(a0, corr, pa * xa0);
        a1 = fmaf(a1, corr, pa * xa1);
        a2 = fmaf(a2, corr, pa * xa2);
        m = nm;
    }

    float inv = 1.0f / (ssum + 1e-16f);
    size_t base = (size_t)n * HID;
    float x0 = g_h[base + lane]      + a0 * inv + sBias[lane];
    float x1 = g_h[base + lane + 32] + a1 * inv + sBias[lane + 32];
    float x2 = g_h[base + lane + 64] + a2 * inv + sBias[lane + 64];
    g_h[base + lane]      = x0;
    g_h[base + lane + 32] = x1;
    g_h[base + lane + 64] = x2;

    float mean = wsum(x0 + x1 + x2) * (1.0f / HID);
    float d0 = x0 - mean, d1 = x1 - mean, d2 = x2 - mean;
    float rstd = rsqrtf(wsum(fmaf(d0, d0, fmaf(d1, d1, d2 * d2))) * (1.0f / HID) + 1e-5f);
    g_hn[base + lane]      = fmaxf(fmaf(d0 * rstd, sG[lane],      sB[lane]),      0.f);
    g_hn[base + lane + 32] = fmaxf(fmaf(d1 * rstd, sG[lane + 32], sB[lane + 32]), 0.f);
    g_hn[base + lane + 64] = fmaxf(fmaf(d2 * rstd, sG[lane + 64], sB[lane + 64]), 0.f);
}

// ---------------- final FC ----------------
__global__ void __launch_bounds__(256) fc_kernel(
    const float* __restrict__ fcW, const float* __restrict__ fcb,
    float* __restrict__ out)
{
    int warp = threadIdx.x >> 5;
    int lane = threadIdx.x & 31;
    int n = blockIdx.x * 8 + warp;
    if (n >= N_NODES) return;
    size_t base = (size_t)n * HID;
    float acc = fmaf(g_hn[base + lane], fcW[lane],
                fmaf(g_hn[base + lane + 32], fcW[lane + 32],
                     g_hn[base + lane + 64] * fcW[lane + 64]));
    acc = wsum(acc);
    if (lane == 0) out[n] = acc + fcb[0];
}

// ---------------- launch ----------------
extern "C" void kernel_launch(void* const* d_in, const int* in_sizes, int n_in,
                              void* d_out, int out_size)
{
    const float* x    = (const float*)d_in[0];
    const void*  ei   = (const void*) d_in[1];
    const float* ew   = (const float*)d_in[2];
    const float* encW = (const float*)d_in[3];
    const float* encb = (const float*)d_in[4];
    const float* Wl   = (const float*)d_in[5];
    const float* bl   = (const float*)d_in[6];
    const float* Wr   = (const float*)d_in[7];
    const float* br   = (const float*)d_in[8];
    const float* We   = (const float*)d_in[9];
    const float* att  = (const float*)d_in[10];
    const float* bias = (const float*)d_in[11];
    const float* lng  = (const float*)d_in[12];
    const float* lnb  = (const float*)d_in[13];
    const float* lnfg = (const float*)d_in[14];
    const float* lnfb = (const float*)d_in[15];
    const float* fcW  = (const float*)d_in[16];
    const float* fcb  = (const float*)d_in[17];
    float*       out  = (float*)d_out;

    void *p_h, *p_hn, *p_xlxr, *p_cnt;
    cudaGetSymbolAddress(&p_h,    g_h);
    cudaGetSymbolAddress(&p_hn,   g_hn);
    cudaGetSymbolAddress(&p_xlxr, g_xlxr);
    cudaGetSymbolAddress(&p_cnt,  g_cnt);

    const int gemm_blocks  = (N_NODES + 63) / 64;     // 782
    const int node_blocks  = (N_NODES + 7) / 8;       // 6250
    const int edge_blocks  = (E_EDGES + 255) / 256;   // 3125

    // CSR build (once per launch, shared by all 4 layers)
    detect_kernel<<<1, 1>>>((const int*)ei);
    cudaMemsetAsync(p_cnt, 0, N_NODES * sizeof(int));
    hist_kernel<<<edge_blocks, 256>>>(ei);
    scan_kernel<<<1, 1024>>>();
    scatter_kernel<<<edge_blocks, 256>>>(ei, ew);

    // encoder + first LN
    gemm2_kernel<F_IN, HID, HID, 16><<<gemm_blocks, 256>>>(
        x, encW, encW, encb, encb, (float*)p_h, N_NODES);
    ln_init_kernel<<<node_blocks, 256>>>((const float*)p_h, lng, lnb, (float*)p_hn);

    for (int i = 0; i < L_LAYERS; i++) {
        gemm2_kernel<HID, 2 * HID, HID, 32><<<gemm_blocks, 256>>>(
            (const float*)p_hn,
            Wl + (size_t)i * HID * HID, Wr + (size_t)i * HID * HID,
            bl + i * HID, br + i * HID, (float*)p_xlxr, N_NODES);

        const float* gnext = (i < L_LAYERS - 1) ? (lng + (i + 1) * HID) : lnfg;
        const float* bnext = (i < L_LAYERS - 1) ? (lnb + (i + 1) * HID) : lnfb;
        gat_fused_kernel<<<node_blocks, 256>>>(
            We + i * HID, att + i * HID, bias + i * HID, gnext, bnext);
    }

    fc_kernel<<<node_blocks, 256>>>(fcW, fcb, out);
}

// round 3
// speedup vs baseline: 1.4233x; 1.4233x over previous
#include <cuda_runtime.h>
#include <cstdint>
#include <math.h>

#define N_NODES 50000
#define E_EDGES 800000
#define F_IN    128
#define HID     96
#define L_LAYERS 4

// ---------------- device scratch ----------------
__device__ __align__(16) float g_h   [N_NODES * HID];
__device__ __align__(16) float g_hn  [N_NODES * HID];
__device__ __align__(16) float g_xlxr[N_NODES * 2 * HID];   // stride 192: [0:96)=xl, [96:192)=xr
__device__ __align__(16) int   g_cnt   [N_NODES];
__device__ __align__(16) int   g_rowptr[N_NODES + 1];
__device__ __align__(16) int   g_cursor[N_NODES];
__device__ __align__(16) int2  g_edge  [E_EDGES];   // (src, ew bits), sorted by dst
__device__ __align__(16) int   g_cdst  [E_EDGES];   // dst per CSR edge
__device__ __align__(16) float g_alpha [E_EDGES];
__device__ int g_is64;

// ---------------- edge_index dtype sniff ----------------
__global__ void detect_kernel(const int* ei32) {
    bool is64 = true;
    #pragma unroll
    for (int i = 0; i < 8; i++) if (ei32[2 * i + 1] != 0) is64 = false;
    g_is64 = is64 ? 1 : 0;
}

__device__ __forceinline__ void load_edge(const void* ei, int e, int& s, int& d) {
    if (g_is64) {
        const long long* p = (const long long*)ei;
        s = (int)p[e]; d = (int)p[E_EDGES + e];
    } else {
        const int* p = (const int*)ei;
        s = p[e]; d = p[E_EDGES + e];
    }
}

// ---------------- CSR build (2 edges/thread for atomic-latency hiding) ----------------
__global__ void __launch_bounds__(256) hist_kernel(const void* ei) {
    int base = (blockIdx.x * blockDim.x + threadIdx.x) * 2;
    #pragma unroll
    for (int i = 0; i < 2; i++) {
        int e = base + i;
        if (e < E_EDGES) {
            int s, d; load_edge(ei, e, s, d);
            atomicAdd(&g_cnt[d], 1);
        }
    }
}

__global__ void __launch_bounds__(1024) scan_kernel() {
    __shared__ int ps[1024];
    int t = threadIdx.x;
    const int CH = (N_NODES + 1023) / 1024;
    int base = t * CH;
    int sum = 0;
    for (int i = 0; i < CH; i++) {
        int idx = base + i;
        if (idx < N_NODES) sum += g_cnt[idx];
    }
    ps[t] = sum;
    __syncthreads();
    for (int off = 1; off < 1024; off <<= 1) {
        int v = (t >= off) ? ps[t - off] : 0;
        __syncthreads();
        ps[t] += v;
        __syncthreads();
    }
    int run = ps[t] - sum;
    for (int i = 0; i < CH; i++) {
        int idx = base + i;
        if (idx < N_NODES) {
            g_rowptr[idx] = run;
            g_cursor[idx] = run;
            run += g_cnt[idx];
        }
    }
    if (t == 0) g_rowptr[N_NODES] = E_EDGES;
}

__global__ void __launch_bounds__(256) scatter_kernel(const void* ei, const float* __restrict__ ew) {
    int base = (blockIdx.x * blockDim.x + threadIdx.x) * 2;
    #pragma unroll
    for (int i = 0; i < 2; i++) {
        int e = base + i;
        if (e < E_EDGES) {
            int s, d; load_edge(ei, e, s, d);
            int p = atomicAdd(&g_cursor[d], 1);
            g_edge[p] = make_int2(s, __float_as_int(ew[e]));
            g_cdst[p] = d;
        }
    }
}

// ---------------- packed-f32x2 helpers ----------------
__device__ __forceinline__ unsigned long long lds64(unsigned addr) {
    unsigned long long v;
    asm volatile("ld.shared.b64 %0, [%1];" : "=l"(v) : "r"(addr));
    return v;
}
__device__ __forceinline__ void ffma2(unsigned long long& d, unsigned long long a, unsigned long long b) {
    asm volatile("fma.rn.f32x2 %0, %1, %2, %0;" : "+l"(d) : "l"(a), "l"(b));
}

// ---------------- GEMM: C[nrows,CW] = A[nrows,K] @ [W1|W2] + [b1|b2] ----------------
template <int K, int CW, int CW1, int CLANES>
__global__ void __launch_bounds__(256) gemm2_kernel(
    const float* __restrict__ A,
    const float* __restrict__ W1, const float* __restrict__ W2,
    const float* __restrict__ b1, const float* __restrict__ b2,
    float* __restrict__ C, int nrows)
{
    constexpr int KCH = 32;
    constexpr int RPB = 64;
    constexpr int RG  = 256 / CLANES;
    constexpr int RPT = RPB / RG;
    constexpr int PS  = CW / 3;

    __shared__ float2 As2[RPB * KCH];
    __shared__ float  Ws[KCH * CW];

    const int tid = threadIdx.x;
    const int cx  = tid % CLANES;
    const int ry  = tid / CLANES;
    const int rowbase = blockIdx.x * RPB;

    unsigned aB = (unsigned)__cvta_generic_to_shared(As2);
    unsigned wB = (unsigned)__cvta_generic_to_shared(Ws);

    unsigned long long acc[RPT][3];
    #pragma unroll
    for (int j = 0; j < RPT; j++)
        #pragma unroll
        for (int c = 0; c < 3; c++) acc[j][c] = 0ULL;

    for (int kc = 0; kc < K; kc += KCH) {
        #pragma unroll
        for (int i = 0; i < 2; i++) {
            int f4  = tid + i * 256;
            int row = f4 >> 3;
            int kk  = (f4 & 7) * 4;
            float4 v = make_float4(0.f, 0.f, 0.f, 0.f);
            int grow = rowbase + row;
            if (grow < nrows) v = *(const float4*)(A + (size_t)grow * K + kc + kk);
            As2[row * KCH + kk + 0] = make_float2(v.x, v.x);
            As2[row * KCH + kk + 1] = make_float2(v.y, v.y);
            As2[row * KCH + kk + 2] = make_float2(v.z, v.z);
            As2[row * KCH + kk + 3] = make_float2(v.w, v.w);
        }
        #pragma unroll
        for (int i = 0; i < (KCH * CW) / 1024; i++) {
            int f = (tid + i * 256) * 4;
            int k = f / CW;
            int c = f % CW;
            float4 v;
            if (c < CW1) v = *(const float4*)(W1 + (size_t)(kc + k) * CW1 + c);
            else         v = *(const float4*)(W2 + (size_t)(kc + k) * (CW - CW1) + (c - CW1));
            *(float4*)(Ws + k * CW + c) = v;
        }
        __syncthreads();

        #pragma unroll 8
        for (int kk = 0; kk < KCH; kk++) {
            unsigned long long av[RPT];
            #pragma unroll
            for (int j = 0; j < RPT; j++)
                av[j] = lds64(aB + (unsigned)(((ry + RG * j) * KCH + kk) << 3));
            unsigned long long wv[3];
            #pragma unroll
            for (int c = 0; c < 3; c++)
                wv[c] = lds64(wB + (unsigned)((kk * CW + 2 * cx + PS * c) << 2));
            #pragma unroll
            for (int j = 0; j < RPT; j++)
                #pragma unroll
                for (int c = 0; c < 3; c++) ffma2(acc[j][c], av[j], wv[c]);
        }
        __syncthreads();
    }

    #pragma unroll
    for (int c = 0; c < 3; c++) {
        int col = 2 * cx + PS * c;
        float bv0, bv1;
        if (col < CW1) { bv0 = b1[col];       bv1 = b1[col + 1]; }
        else           { bv0 = b2[col - CW1]; bv1 = b2[col - CW1 + 1]; }
        #pragma unroll
        for (int j = 0; j < RPT; j++) {
            int grow = rowbase + ry + RG * j;
            if (grow < nrows) {
                float lo, hi;
                asm("mov.b64 {%0,%1}, %2;" : "=f"(lo), "=f"(hi) : "l"(acc[j][c]));
                *(float2*)(C + (size_t)grow * CW + col) = make_float2(lo + bv0, hi + bv1);
            }
        }
    }
}

// ---------------- warp reduce ----------------
__device__ __forceinline__ float wsum(float v) {
    #pragma unroll
    for (int o = 16; o > 0; o >>= 1) v += __shfl_xor_sync(0xffffffffu, v, o);
    return v;
}
__device__ __forceinline__ float wmax(float v) {
    #pragma unroll
    for (int o = 16; o > 0; o >>= 1) v = fmaxf(v, __shfl_xor_sync(0xffffffffu, v, o));
    return v;
}

// ---------------- initial LayerNorm + ReLU (h -> hn) ----------------
__global__ void __launch_bounds__(256) ln_init_kernel(
    const float* __restrict__ h,
    const float* __restrict__ g, const float* __restrict__ b,
    float* __restrict__ hn)
{
    int warp = threadIdx.x >> 5;
    int lane = threadIdx.x & 31;
    int n = blockIdx.x * 8 + warp;
    if (n >= N_NODES) return;
    size_t base = (size_t)n * HID;

    float v0 = h[base + lane], v1 = h[base + lane + 32], v2 = h[base + lane + 64];
    float mean = wsum(v0 + v1 + v2) * (1.0f / HID);
    float d0 = v0 - mean, d1 = v1 - mean, d2 = v2 - mean;
    float rstd = rsqrtf(wsum(fmaf(d0, d0, fmaf(d1, d1, d2 * d2))) * (1.0f / HID) + 1e-5f);
    hn[base + lane]      = fmaxf(fmaf(d0 * rstd, g[lane],      b[lane]),      0.f);
    hn[base + lane + 32] = fmaxf(fmaf(d1 * rstd, g[lane + 32], b[lane + 32]), 0.f);
    hn[base + lane + 64] = fmaxf(fmaf(d2 * rstd, g[lane + 64], b[lane + 64]), 0.f);
}

// ---------------- K1: edge-parallel alpha over CSR edges (8 threads/edge) --------
__global__ void __launch_bounds__(256) edge_alpha_kernel(
    const float* __restrict__ We, const float* __restrict__ att)
{
    __shared__ float sWe[HID], sAtt[HID];
    if (threadIdx.x < HID) { sWe[threadIdx.x] = We[threadIdx.x]; sAtt[threadIdx.x] = att[threadIdx.x]; }
    __syncthreads();

    int gid  = blockIdx.x * blockDim.x + threadIdx.x;
    int e    = gid >> 3;
    int lane8 = gid & 7;
    if (e >= E_EDGES) return;

    int2 ed = g_edge[e];
    int   src = ed.x;
    float w   = __int_as_float(ed.y);
    int   dst = g_cdst[e];                 // sorted: consecutive edges share dst -> L1 hits
    const float* xl = g_xlxr + (size_t)src * 192;
    const float* xr = g_xlxr + (size_t)dst * 192 + 96;

    float part = 0.f;
    #pragma unroll
    for (int c = 0; c < 3; c++) {
        int k = c * 32 + lane8 * 4;
        float4 a  = *(const float4*)(xl + k);
        float4 b  = *(const float4*)(xr + k);
        float4 wv = *(const float4*)(sWe + k);
        float4 tv = *(const float4*)(sAtt + k);
        float e0 = a.x + b.x + w * wv.x; e0 = e0 > 0.f ? e0 : 0.2f * e0; part = fmaf(e0, tv.x, part);
        float e1 = a.y + b.y + w * wv.y; e1 = e1 > 0.f ? e1 : 0.2f * e1; part = fmaf(e1, tv.y, part);
        float e2 = a.z + b.z + w * wv.z; e2 = e2 > 0.f ? e2 : 0.2f * e2; part = fmaf(e2, tv.z, part);
        float e3 = a.w + b.w + w * wv.w; e3 = e3 > 0.f ? e3 : 0.2f * e3; part = fmaf(e3, tv.w, part);
    }
    part += __shfl_xor_sync(0xffffffffu, part, 4);
    part += __shfl_xor_sync(0xffffffffu, part, 2);
    part += __shfl_xor_sync(0xffffffffu, part, 1);

    if (lane8 == 0) g_alpha[e] = part;
}

// ---------------- K2: node-parallel softmax + aggregate + residual + LN + ReLU ----
__global__ void __launch_bounds__(256) gat_reduce_kernel(
    const float* __restrict__ bias,
    const float* __restrict__ lg, const float* __restrict__ lb)
{
    __shared__ float sBias[HID], sG[HID], sB[HID];
    int t = threadIdx.x;
    if (t < HID) { sBias[t] = bias[t]; sG[t] = lg[t]; sB[t] = lb[t]; }
    __syncthreads();

    int warp = t >> 5, lane = t & 31;
    int n = blockIdx.x * 8 + warp;
    if (n >= N_NODES) return;

    int r0 = g_rowptr[n], r1 = g_rowptr[n + 1];

    // ---- softmax stats: lane-parallel over this node's contiguous alpha segment
    float lm = -INFINITY;
    for (int p = r0 + lane; p < r1; p += 32) lm = fmaxf(lm, g_alpha[p]);
    float m = wmax(lm);

    float lsum = 0.f;
    for (int p = r0 + lane; p < r1; p += 32) lsum += __expf(g_alpha[p] - m);
    float inv = 1.0f / (wsum(lsum) + 1e-16f);

    // ---- aggregation: weights broadcast via shfl, gathers fully pipelined
    float a0 = 0.f, a1 = 0.f, a2 = 0.f;
    for (int p0 = r0; p0 < r1; p0 += 32) {
        int p = p0 + lane;
        bool v = p < r1;
        float wi = v ? __expf(g_alpha[p] - m) * inv : 0.f;
        int   si = v ? g_edge[p].x : 0;
        int cnt = min(32, r1 - p0);

        int j = 0;
        for (; j + 4 <= cnt; j += 4) {
            float w0 = __shfl_sync(0xffffffffu, wi, j + 0);
            float w1 = __shfl_sync(0xffffffffu, wi, j + 1);
            float w2 = __shfl_sync(0xffffffffu, wi, j + 2);
            float w3 = __shfl_sync(0xffffffffu, wi, j + 3);
            const float* x0p = g_xlxr + (size_t)__shfl_sync(0xffffffffu, si, j + 0) * 192;
            const float* x1p = g_xlxr + (size_t)__shfl_sync(0xffffffffu, si, j + 1) * 192;
            const float* x2p = g_xlxr + (size_t)__shfl_sync(0xffffffffu, si, j + 2) * 192;
            const float* x3p = g_xlxr + (size_t)__shfl_sync(0xffffffffu, si, j + 3) * 192;
            float v00 = x0p[lane], v01 = x0p[lane + 32], v02 = x0p[lane + 64];
            float v10 = x1p[lane], v11 = x1p[lane + 32], v12 = x1p[lane + 64];
            float v20 = x2p[lane], v21 = x2p[lane + 32], v22 = x2p[lane + 64];
            float v30 = x3p[lane], v31 = x3p[lane + 32], v32 = x3p[lane + 64];
            a0 = fmaf(w0, v00, a0); a1 = fmaf(w0, v01, a1); a2 = fmaf(w0, v02, a2);
            a0 = fmaf(w1, v10, a0); a1 = fmaf(w1, v11, a1); a2 = fmaf(w1, v12, a2);
            a0 = fmaf(w2, v20, a0); a1 = fmaf(w2, v21, a1); a2 = fmaf(w2, v22, a2);
            a0 = fmaf(w3, v30, a0); a1 = fmaf(w3, v31, a1); a2 = fmaf(w3, v32, a2);
        }
        for (; j < cnt; j++) {
            float w = __shfl_sync(0xffffffffu, wi, j);
            const float* xp = g_xlxr + (size_t)__shfl_sync(0xffffffffu, si, j) * 192;
            a0 = fmaf(w, xp[lane],      a0);
            a1 = fmaf(w, xp[lane + 32], a1);
            a2 = fmaf(w, xp[lane + 64], a2);
        }
    }

    // ---- residual + bias + LayerNorm + ReLU
    size_t base = (size_t)n * HID;
    float x0 = g_h[base + lane]      + a0 + sBias[lane];
    float x1 = g_h[base + lane + 32] + a1 + sBias[lane + 32];
    float x2 = g_h[base + lane + 64] + a2 + sBias[lane + 64];
    g_h[base + lane]      = x0;
    g_h[base + lane + 32] = x1;
    g_h[base + lane + 64] = x2;

    float mean = wsum(x0 + x1 + x2) * (1.0f / HID);
    float d0 = x0 - mean, d1 = x1 - mean, d2 = x2 - mean;
    float rstd = rsqrtf(wsum(fmaf(d0, d0, fmaf(d1, d1, d2 * d2))) * (1.0f / HID) + 1e-5f);
    g_hn[base + lane]      = fmaxf(fmaf(d0 * rstd, sG[lane],      sB[lane]),      0.f);
    g_hn[base + lane + 32] = fmaxf(fmaf(d1 * rstd, sG[lane + 32], sB[lane + 32]), 0.f);
    g_hn[base + lane + 64] = fmaxf(fmaf(d2 * rstd, sG[lane + 64], sB[lane + 64]), 0.f);
}

// ---------------- final FC ----------------
__global__ void __launch_bounds__(256) fc_kernel(
    const float* __restrict__ fcW, const float* __restrict__ fcb,
    float* __restrict__ out)
{
    int warp = threadIdx.x >> 5;
    int lane = threadIdx.x & 31;
    int n = blockIdx.x * 8 + warp;
    if (n >= N_NODES) return;
    size_t base = (size_t)n * HID;
    float acc = fmaf(g_hn[base + lane], fcW[lane],
                fmaf(g_hn[base + lane + 32], fcW[lane + 32],
                     g_hn[base + lane + 64] * fcW[lane + 64]));
    acc = wsum(acc);
    if (lane == 0) out[n] = acc + fcb[0];
}

// ---------------- launch ----------------
extern "C" void kernel_launch(void* const* d_in, const int* in_sizes, int n_in,
                              void* d_out, int out_size)
{
    const float* x    = (const float*)d_in[0];
    const void*  ei   = (const void*) d_in[1];
    const float* ew   = (const float*)d_in[2];
    const float* encW = (const float*)d_in[3];
    const float* encb = (const float*)d_in[4];
    const float* Wl   = (const float*)d_in[5];
    const float* bl   = (const float*)d_in[6];
    const float* Wr   = (const float*)d_in[7];
    const float* br   = (const float*)d_in[8];
    const float* We   = (const float*)d_in[9];
    const float* att  = (const float*)d_in[10];
    const float* bias = (const float*)d_in[11];
    const float* lng  = (const float*)d_in[12];
    const float* lnb  = (const float*)d_in[13];
    const float* lnfg = (const float*)d_in[14];
    const float* lnfb = (const float*)d_in[15];
    const float* fcW  = (const float*)d_in[16];
    const float* fcb  = (const float*)d_in[17];
    float*       out  = (float*)d_out;

    void *p_h, *p_hn, *p_cnt;
    cudaGetSymbolAddress(&p_h,   g_h);
    cudaGetSymbolAddress(&p_hn,  g_hn);
    cudaGetSymbolAddress(&p_cnt, g_cnt);
    void* p_xlxr; cudaGetSymbolAddress(&p_xlxr, g_xlxr);

    const int gemm_blocks  = (N_NODES + 63) / 64;       // 782
    const int node_blocks  = (N_NODES + 7) / 8;         // 6250
    const int edge2_blocks = (E_EDGES / 2 + 255) / 256; // 1563
    const int edge8_blocks = (E_EDGES * 8) / 256;       // 25000

    // CSR build (once per launch, shared by all 4 layers)
    detect_kernel<<<1, 1>>>((const int*)ei);
    cudaMemsetAsync(p_cnt, 0, N_NODES * sizeof(int));
    hist_kernel<<<edge2_blocks, 256>>>(ei);
    scan_kernel<<<1, 1024>>>();
    scatter_kernel<<<edge2_blocks, 256>>>(ei, ew);

    // encoder + first LN
    gemm2_kernel<F_IN, HID, HID, 16><<<gemm_blocks, 256>>>(
        x, encW, encW, encb, encb, (float*)p_h, N_NODES);
    ln_init_kernel<<<node_blocks, 256>>>((const float*)p_h, lng, lnb, (float*)p_hn);

    for (int i = 0; i < L_LAYERS; i++) {
        gemm2_kernel<HID, 2 * HID, HID, 32><<<gemm_blocks, 256>>>(
            (const float*)p_hn,
            Wl + (size_t)i * HID * HID, Wr + (size_t)i * HID * HID,
            bl + i * HID, br + i * HID, (float*)p_xlxr, N_NODES);

        edge_alpha_kernel<<<edge8_blocks, 256>>>(We + i * HID, att + i * HID);

        const float* gnext = (i < L_LAYERS - 1) ? (lng + (i + 1) * HID) : lnfg;
        const float* bnext = (i < L_LAYERS - 1) ? (lnb + (i + 1) * HID) : lnfb;
        gat_reduce_kernel<<<node_blocks, 256>>>(bias + i * HID, gnext, bnext);
    }

    fc_kernel<<<node_blocks, 256>>>(fcW, fcb, out);
}

// round 4
// speedup vs baseline: 1.4425x; 1.0135x over previous
#include <cuda_runtime.h>
#include <cstdint>
#include <math.h>

#define N_NODES 50000
#define E_EDGES 800000
#define F_IN    128
#define HID     96
#define L_LAYERS 4

// ---------------- device scratch ----------------
__device__ __align__(16) float g_h   [N_NODES * HID];
__device__ __align__(16) float g_hn  [N_NODES * HID];
__device__ __align__(16) float g_xlxr[N_NODES * 2 * HID];   // stride 192: [0:96)=xl, [96:192)=xr
__device__ __align__(16) int   g_cnt   [N_NODES];
__device__ __align__(16) int   g_rowptr[N_NODES + 1];
__device__ __align__(16) int   g_cursor[N_NODES];
__device__ __align__(16) int2  g_edge  [E_EDGES];   // (src, ew bits), sorted by dst
__device__ int g_is64;

// ---------------- edge_index dtype sniff ----------------
__global__ void detect_kernel(const int* ei32) {
    bool is64 = true;
    #pragma unroll
    for (int i = 0; i < 8; i++) if (ei32[2 * i + 1] != 0) is64 = false;
    g_is64 = is64 ? 1 : 0;
}

__device__ __forceinline__ void load_edge(const void* ei, int e, int& s, int& d) {
    if (g_is64) {
        const long long* p = (const long long*)ei;
        s = (int)p[e]; d = (int)p[E_EDGES + e];
    } else {
        const int* p = (const int*)ei;
        s = p[e]; d = p[E_EDGES + e];
    }
}

// ---------------- CSR build ----------------
__global__ void __launch_bounds__(256) hist_kernel(const void* ei) {
    int base = (blockIdx.x * blockDim.x + threadIdx.x) * 2;
    #pragma unroll
    for (int i = 0; i < 2; i++) {
        int e = base + i;
        if (e < E_EDGES) {
            int s, d; load_edge(ei, e, s, d);
            atomicAdd(&g_cnt[d], 1);
        }
    }
}

__global__ void __launch_bounds__(1024) scan_kernel() {
    __shared__ int ps[1024];
    int t = threadIdx.x;
    const int CH = (N_NODES + 1023) / 1024;
    int base = t * CH;
    int sum = 0;
    for (int i = 0; i < CH; i++) {
        int idx = base + i;
        if (idx < N_NODES) sum += g_cnt[idx];
    }
    ps[t] = sum;
    __syncthreads();
    for (int off = 1; off < 1024; off <<= 1) {
        int v = (t >= off) ? ps[t - off] : 0;
        __syncthreads();
        ps[t] += v;
        __syncthreads();
    }
    int run = ps[t] - sum;
    for (int i = 0; i < CH; i++) {
        int idx = base + i;
        if (idx < N_NODES) {
            g_rowptr[idx] = run;
            g_cursor[idx] = run;
            run += g_cnt[idx];
        }
    }
    if (t == 0) g_rowptr[N_NODES] = E_EDGES;
}

__global__ void __launch_bounds__(256) scatter_kernel(const void* ei, const float* __restrict__ ew) {
    int base = (blockIdx.x * blockDim.x + threadIdx.x) * 2;
    #pragma unroll
    for (int i = 0; i < 2; i++) {
        int e = base + i;
        if (e < E_EDGES) {
            int s, d; load_edge(ei, e, s, d);
            int p = atomicAdd(&g_cursor[d], 1);
            g_edge[p] = make_int2(s, __float_as_int(ew[e]));
        }
    }
}

// ---------------- packed-f32x2 helpers ----------------
__device__ __forceinline__ unsigned long long lds64(unsigned addr) {
    unsigned long long v;
    asm volatile("ld.shared.b64 %0, [%1];" : "=l"(v) : "r"(addr));
    return v;
}
__device__ __forceinline__ void ffma2(unsigned long long& d, unsigned long long a, unsigned long long b) {
    asm volatile("fma.rn.f32x2 %0, %1, %2, %0;" : "+l"(d) : "l"(a), "l"(b));
}

// ---------------- GEMM: C[nrows,CW] = A[nrows,K] @ [W1|W2] + [b1|b2] ----------------
template <int K, int CW, int CW1, int CLANES>
__global__ void __launch_bounds__(256) gemm2_kernel(
    const float* __restrict__ A,
    const float* __restrict__ W1, const float* __restrict__ W2,
    const float* __restrict__ b1, const float* __restrict__ b2,
    float* __restrict__ C, int nrows)
{
    constexpr int KCH = 32;
    constexpr int RPB = 64;
    constexpr int RG  = 256 / CLANES;
    constexpr int RPT = RPB / RG;
    constexpr int PS  = CW / 3;

    __shared__ float2 As2[RPB * KCH];
    __shared__ float  Ws[KCH * CW];

    const int tid = threadIdx.x;
    const int cx  = tid % CLANES;
    const int ry  = tid / CLANES;
    const int rowbase = blockIdx.x * RPB;

    unsigned aB = (unsigned)__cvta_generic_to_shared(As2);
    unsigned wB = (unsigned)__cvta_generic_to_shared(Ws);

    unsigned long long acc[RPT][3];
    #pragma unroll
    for (int j = 0; j < RPT; j++)
        #pragma unroll
        for (int c = 0; c < 3; c++) acc[j][c] = 0ULL;

    for (int kc = 0; kc < K; kc += KCH) {
        #pragma unroll
        for (int i = 0; i < 2; i++) {
            int f4  = tid + i * 256;
            int row = f4 >> 3;
            int kk  = (f4 & 7) * 4;
            float4 v = make_float4(0.f, 0.f, 0.f, 0.f);
            int grow = rowbase + row;
            if (grow < nrows) v = *(const float4*)(A + (size_t)grow * K + kc + kk);
            As2[row * KCH + kk + 0] = make_float2(v.x, v.x);
            As2[row * KCH + kk + 1] = make_float2(v.y, v.y);
            As2[row * KCH + kk + 2] = make_float2(v.z, v.z);
            As2[row * KCH + kk + 3] = make_float2(v.w, v.w);
        }
        #pragma unroll
        for (int i = 0; i < (KCH * CW) / 1024; i++) {
            int f = (tid + i * 256) * 4;
            int k = f / CW;
            int c = f % CW;
            float4 v;
            if (c < CW1) v = *(const float4*)(W1 + (size_t)(kc + k) * CW1 + c);
            else         v = *(const float4*)(W2 + (size_t)(kc + k) * (CW - CW1) + (c - CW1));
            *(float4*)(Ws + k * CW + c) = v;
        }
        __syncthreads();

        #pragma unroll 8
        for (int kk = 0; kk < KCH; kk++) {
            unsigned long long av[RPT];
            #pragma unroll
            for (int j = 0; j < RPT; j++)
                av[j] = lds64(aB + (unsigned)(((ry + RG * j) * KCH + kk) << 3));
            unsigned long long wv[3];
            #pragma unroll
            for (int c = 0; c < 3; c++)
                wv[c] = lds64(wB + (unsigned)((kk * CW + 2 * cx + PS * c) << 2));
            #pragma unroll
            for (int j = 0; j < RPT; j++)
                #pragma unroll
                for (int c = 0; c < 3; c++) ffma2(acc[j][c], av[j], wv[c]);
        }
        __syncthreads();
    }

    #pragma unroll
    for (int c = 0; c < 3; c++) {
        int col = 2 * cx + PS * c;
        float bv0, bv1;
        if (col < CW1) { bv0 = b1[col];       bv1 = b1[col + 1]; }
        else           { bv0 = b2[col - CW1]; bv1 = b2[col - CW1 + 1]; }
        #pragma unroll
        for (int j = 0; j < RPT; j++) {
            int grow = rowbase + ry + RG * j;
            if (grow < nrows) {
                float lo, hi;
                asm("mov.b64 {%0,%1}, %2;" : "=f"(lo), "=f"(hi) : "l"(acc[j][c]));
                *(float2*)(C + (size_t)grow * CW + col) = make_float2(lo + bv0, hi + bv1);
            }
        }
    }
}

// ---------------- warp reduce ----------------
__device__ __forceinline__ float wsum(float v) {
    #pragma unroll
    for (int o = 16; o > 0; o >>= 1) v += __shfl_xor_sync(0xffffffffu, v, o);
    return v;
}
__device__ __forceinline__ float wmax(float v) {
    #pragma unroll
    for (int o = 16; o > 0; o >>= 1) v = fmaxf(v, __shfl_xor_sync(0xffffffffu, v, o));
    return v;
}

// ---------------- initial LayerNorm + ReLU (h -> hn) ----------------
__global__ void __launch_bounds__(256) ln_init_kernel(
    const float* __restrict__ h,
    const float* __restrict__ g, const float* __restrict__ b,
    float* __restrict__ hn)
{
    int warp = threadIdx.x >> 5;
    int lane = threadIdx.x & 31;
    int n = blockIdx.x * 8 + warp;
    if (n >= N_NODES) return;
    size_t base = (size_t)n * HID;

    float v0 = h[base + lane], v1 = h[base + lane + 32], v2 = h[base + lane + 64];
    float mean = wsum(v0 + v1 + v2) * (1.0f / HID);
    float d0 = v0 - mean, d1 = v1 - mean, d2 = v2 - mean;
    float rstd = rsqrtf(wsum(fmaf(d0, d0, fmaf(d1, d1, d2 * d2))) * (1.0f / HID) + 1e-5f);
    hn[base + lane]      = fmaxf(fmaf(d0 * rstd, g[lane],      b[lane]),      0.f);
    hn[base + lane + 32] = fmaxf(fmaf(d1 * rstd, g[lane + 32], b[lane + 32]), 0.f);
    hn[base + lane + 64] = fmaxf(fmaf(d2 * rstd, g[lane + 64], b[lane + 64]), 0.f);
}

// ---------------- fused GAT layer: chunked softmax + aggregate + residual + LN ----
// Warp per node. Per 32-edge chunk:
//   pass A: coalesced per-edge alpha (independent reduce trees, 2-edge unroll)
//   chunk-level online-softmax merge (one exp correction per chunk)
//   pass B: aggregation re-gathering the same rows (L1-hot, same launch)
__global__ void __launch_bounds__(256) gat_fused_kernel(
    const float* __restrict__ We,  const float* __restrict__ att,
    const float* __restrict__ bias,
    const float* __restrict__ lg,  const float* __restrict__ lb)
{
    __shared__ float sWe[HID], sAtt[HID], sBias[HID], sG[HID], sB[HID];
    int t = threadIdx.x;
    if (t < HID) {
        sWe[t] = We[t]; sAtt[t] = att[t]; sBias[t] = bias[t];
        sG[t] = lg[t];  sB[t]  = lb[t];
    }
    __syncthreads();

    int warp = t >> 5, lane = t & 31;
    int n = blockIdx.x * 8 + warp;
    if (n >= N_NODES) return;

    int r0 = g_rowptr[n], r1 = g_rowptr[n + 1];
    const float* xrp = g_xlxr + (size_t)n * 192 + 96;
    float xr0 = xrp[lane], xr1 = xrp[lane + 32], xr2 = xrp[lane + 64];
    float we0 = sWe[lane],  we1 = sWe[lane + 32],  we2 = sWe[lane + 64];
    float at0 = sAtt[lane], at1 = sAtt[lane + 32], at2 = sAtt[lane + 64];

    float m = -INFINITY, ssum = 0.f;
    float a0 = 0.f, a1 = 0.f, a2 = 0.f;

    for (int c0 = r0; c0 < r1; c0 += 32) {
        int cnt = min(32, r1 - c0);
        int p = c0 + lane;
        int   si = 0;
        float wE = 0.f;
        if (lane < cnt) {
            int2 ed = g_edge[p];
            si = ed.x;
            wE = __int_as_float(ed.y);
        }

        // ---- pass A: alpha per edge (coalesced row loads, independent reduces)
        float myal = -INFINITY;
        int j = 0;
        for (; j + 2 <= cnt; j += 2) {
            int   sa = __shfl_sync(0xffffffffu, si, j);
            int   sb = __shfl_sync(0xffffffffu, si, j + 1);
            float wa = __shfl_sync(0xffffffffu, wE, j);
            float wb = __shfl_sync(0xffffffffu, wE, j + 1);
            const float* xa = g_xlxr + (size_t)sa * 192;
            const float* xb = g_xlxr + (size_t)sb * 192;
            float xa0 = xa[lane], xa1 = xa[lane + 32], xa2 = xa[lane + 64];
            float xb0 = xb[lane], xb1 = xb[lane + 32], xb2 = xb[lane + 64];

            float e0 = xa0 + xr0 + wa * we0; e0 = e0 > 0.f ? e0 : 0.2f * e0;
            float e1 = xa1 + xr1 + wa * we1; e1 = e1 > 0.f ? e1 : 0.2f * e1;
            float e2 = xa2 + xr2 + wa * we2; e2 = e2 > 0.f ? e2 : 0.2f * e2;
            float ta = fmaf(e0, at0, fmaf(e1, at1, e2 * at2));

            float f0 = xb0 + xr0 + wb * we0; f0 = f0 > 0.f ? f0 : 0.2f * f0;
            float f1 = xb1 + xr1 + wb * we1; f1 = f1 > 0.f ? f1 : 0.2f * f1;
            float f2 = xb2 + xr2 + wb * we2; f2 = f2 > 0.f ? f2 : 0.2f * f2;
            float tb = fmaf(f0, at0, fmaf(f1, at1, f2 * at2));

            #pragma unroll
            for (int o = 16; o > 0; o >>= 1) {
                ta += __shfl_xor_sync(0xffffffffu, ta, o);
                tb += __shfl_xor_sync(0xffffffffu, tb, o);
            }
            myal = (lane == j)     ? ta : myal;
            myal = (lane == j + 1) ? tb : myal;
        }
        if (j < cnt) {
            int   sa = __shfl_sync(0xffffffffu, si, j);
            float wa = __shfl_sync(0xffffffffu, wE, j);
            const float* xa = g_xlxr + (size_t)sa * 192;
            float xa0 = xa[lane], xa1 = xa[lane + 32], xa2 = xa[lane + 64];
            float e0 = xa0 + xr0 + wa * we0; e0 = e0 > 0.f ? e0 : 0.2f * e0;
            float e1 = xa1 + xr1 + wa * we1; e1 = e1 > 0.f ? e1 : 0.2f * e1;
            float e2 = xa2 + xr2 + wa * we2; e2 = e2 > 0.f ? e2 : 0.2f * e2;
            float ta = fmaf(e0, at0, fmaf(e1, at1, e2 * at2));
            #pragma unroll
            for (int o = 16; o > 0; o >>= 1) ta += __shfl_xor_sync(0xffffffffu, ta, o);
            myal = (lane == j) ? ta : myal;
        }

        // ---- chunk-level online softmax merge (one correction per chunk)
        float cm = wmax(myal);                 // lanes >= cnt hold -INF
        float nm = fmaxf(m, cm);
        float corr = __expf(m - nm);           // m=-INF first chunk -> 0, no NaN
        ssum *= corr; a0 *= corr; a1 *= corr; a2 *= corr;
        float wexp = (lane < cnt) ? __expf(myal - nm) : 0.f;
        ssum += wsum(wexp);
        m = nm;

        // ---- pass B: aggregation, rows L1-hot from pass A
        int jj = 0;
        for (; jj + 4 <= cnt; jj += 4) {
            float w0 = __shfl_sync(0xffffffffu, wexp, jj + 0);
            float w1 = __shfl_sync(0xffffffffu, wexp, jj + 1);
            float w2 = __shfl_sync(0xffffffffu, wexp, jj + 2);
            float w3 = __shfl_sync(0xffffffffu, wexp, jj + 3);
            const float* x0p = g_xlxr + (size_t)__shfl_sync(0xffffffffu, si, jj + 0) * 192;
            const float* x1p = g_xlxr + (size_t)__shfl_sync(0xffffffffu, si, jj + 1) * 192;
            const float* x2p = g_xlxr + (size_t)__shfl_sync(0xffffffffu, si, jj + 2) * 192;
            const float* x3p = g_xlxr + (size_t)__shfl_sync(0xffffffffu, si, jj + 3) * 192;
            float v00 = x0p[lane], v01 = x0p[lane + 32], v02 = x0p[lane + 64];
            float v10 = x1p[lane], v11 = x1p[lane + 32], v12 = x1p[lane + 64];
            float v20 = x2p[lane], v21 = x2p[lane + 32], v22 = x2p[lane + 64];
            float v30 = x3p[lane], v31 = x3p[lane + 32], v32 = x3p[lane + 64];
            a0 = fmaf(w0, v00, a0); a1 = fmaf(w0, v01, a1); a2 = fmaf(w0, v02, a2);
            a0 = fmaf(w1, v10, a0); a1 = fmaf(w1, v11, a1); a2 = fmaf(w1, v12, a2);
            a0 = fmaf(w2, v20, a0); a1 = fmaf(w2, v21, a1); a2 = fmaf(w2, v22, a2);
            a0 = fmaf(w3, v30, a0); a1 = fmaf(w3, v31, a1); a2 = fmaf(w3, v32, a2);
        }
        for (; jj < cnt; jj++) {
            float w = __shfl_sync(0xffffffffu, wexp, jj);
            const float* xp = g_xlxr + (size_t)__shfl_sync(0xffffffffu, si, jj) * 192;
            a0 = fmaf(w, xp[lane],      a0);
            a1 = fmaf(w, xp[lane + 32], a1);
            a2 = fmaf(w, xp[lane + 64], a2);
        }
    }

    float inv = 1.0f / (ssum + 1e-16f);
    a0 *= inv; a1 *= inv; a2 *= inv;

    // ---- residual + bias + LayerNorm + ReLU
    size_t base = (size_t)n * HID;
    float x0 = g_h[base + lane]      + a0 + sBias[lane];
    float x1 = g_h[base + lane + 32] + a1 + sBias[lane + 32];
    float x2 = g_h[base + lane + 64] + a2 + sBias[lane + 64];
    g_h[base + lane]      = x0;
    g_h[base + lane + 32] = x1;
    g_h[base + lane + 64] = x2;

    float mean = wsum(x0 + x1 + x2) * (1.0f / HID);
    float d0 = x0 - mean, d1 = x1 - mean, d2 = x2 - mean;
    float rstd = rsqrtf(wsum(fmaf(d0, d0, fmaf(d1, d1, d2 * d2))) * (1.0f / HID) + 1e-5f);
    g_hn[base + lane]      = fmaxf(fmaf(d0 * rstd, sG[lane],      sB[lane]),      0.f);
    g_hn[base + lane + 32] = fmaxf(fmaf(d1 * rstd, sG[lane + 32], sB[lane + 32]), 0.f);
    g_hn[base + lane + 64] = fmaxf(fmaf(d2 * rstd, sG[lane + 64], sB[lane + 64]), 0.f);
}

// ---------------- final FC ----------------
__global__ void __launch_bounds__(256) fc_kernel(
    const float* __restrict__ fcW, const float* __restrict__ fcb,
    float* __restrict__ out)
{
    int warp = threadIdx.x >> 5;
    int lane = threadIdx.x & 31;
    int n = blockIdx.x * 8 + warp;
    if (n >= N_NODES) return;
    size_t base = (size_t)n * HID;
    float acc = fmaf(g_hn[base + lane], fcW[lane],
                fmaf(g_hn[base + lane + 32], fcW[lane + 32],
                     g_hn[base + lane + 64] * fcW[lane + 64]));
    acc = wsum(acc);
    if (lane == 0) out[n] = acc + fcb[0];
}

// ---------------- launch ----------------
extern "C" void kernel_launch(void* const* d_in, const int* in_sizes, int n_in,
                              void* d_out, int out_size)
{
    const float* x    = (const float*)d_in[0];
    const void*  ei   = (const void*) d_in[1];
    const float* ew   = (const float*)d_in[2];
    const float* encW = (const float*)d_in[3];
    const float* encb = (const float*)d_in[4];
    const float* Wl   = (const float*)d_in[5];
    const float* bl   = (const float*)d_in[6];
    const float* Wr   = (const float*)d_in[7];
    const float* br   = (const float*)d_in[8];
    const float* We   = (const float*)d_in[9];
    const float* att  = (const float*)d_in[10];
    const float* bias = (const float*)d_in[11];
    const float* lng  = (const float*)d_in[12];
    const float* lnb  = (const float*)d_in[13];
    const float* lnfg = (const float*)d_in[14];
    const float* lnfb = (const float*)d_in[15];
    const float* fcW  = (const float*)d_in[16];
    const float* fcb  = (const float*)d_in[17];
    float*       out  = (float*)d_out;

    void *p_h, *p_hn, *p_cnt, *p_xlxr;
    cudaGetSymbolAddress(&p_h,    g_h);
    cudaGetSymbolAddress(&p_hn,   g_hn);
    cudaGetSymbolAddress(&p_cnt,  g_cnt);
    cudaGetSymbolAddress(&p_xlxr, g_xlxr);

    const int gemm_blocks  = (N_NODES + 63) / 64;       // 782
    const int node_blocks  = (N_NODES + 7) / 8;         // 6250
    const int edge2_blocks = (E_EDGES / 2 + 255) / 256; // 1563

    // CSR build (once per launch, shared by all 4 layers)
    detect_kernel<<<1, 1>>>((const int*)ei);
    cudaMemsetAsync(p_cnt, 0, N_NODES * sizeof(int));
    hist_kernel<<<edge2_blocks, 256>>>(ei);
    scan_kernel<<<1, 1024>>>();
    scatter_kernel<<<edge2_blocks, 256>>>(ei, ew);

    // encoder + first LN
    gemm2_kernel<F_IN, HID, HID, 16><<<gemm_blocks, 256>>>(
        x, encW, encW, encb, encb, (float*)p_h, N_NODES);
    ln_init_kernel<<<node_blocks, 256>>>((const float*)p_h, lng, lnb, (float*)p_hn);

    for (int i = 0; i < L_LAYERS; i++) {
        gemm2_kernel<HID, 2 * HID, HID, 32><<<gemm_blocks, 256>>>(
            (const float*)p_hn,
            Wl + (size_t)i * HID * HID, Wr + (size_t)i * HID * HID,
            bl + i * HID, br + i * HID, (float*)p_xlxr, N_NODES);

        const float* gnext = (i < L_LAYERS - 1) ? (lng + (i + 1) * HID) : lnfg;
        const float* bnext = (i < L_LAYERS - 1) ? (lnb + (i + 1) * HID) : lnfb;
        gat_fused_kernel<<<node_blocks, 256>>>(
            We + i * HID, att + i * HID, bias + i * HID, gnext, bnext);
    }

    fc_kernel<<<node_blocks, 256>>>(fcW, fcb, out);
}